// round 13
// baseline (speedup 1.0000x reference)
#include <cuda_runtime.h>
#include <cstdint>

// ---------------- problem constants ----------------
#define MTOT 16384
#define KTOT 1024
#define NTOT 1024

#define BM 128
#define BN 128
#define KT 16             /* 64-byte k-tiles */
#define MT (MTOT / BM)    /* 128 m-tiles  */
#define NT (NTOT / BN)    /* 8 n-tiles    */

#define STAGES 4
#define TILE_BYTES (128 * 64)   /* 8192 */

#define WPREP_BLOCKS 256        /* 4 output channels per 256-thread block; scheduled FIRST */
#define QUANT_BLOCKS 2048       /* 2 physical 16B chunks per thread */

// ---------------- scratch (device globals; no allocation allowed) ----------------
__device__ __align__(16) unsigned char g_xq[(size_t)MTOT * KTOT];  // 16 MB int8, tiled+swizzled
__device__ __align__(16) unsigned char g_wb[(size_t)NTOT * KTOT];  // 1 MB int8, tiled+swizzled
__device__ float g_alpha[NTOT];
__device__ float g_beta[NTOT];

// Tile layout: [128 rows r][64 k-bytes] packed as 64 physical rows of 128B:
//   off(r, kc16) = (r>>1)*128 + ( (((r&1)<<6) | kc16) ^ (((r>>1)&7)<<4) )
__device__ __forceinline__ uint32_t tile_off(uint32_t r, uint32_t kc16) {
    uint32_t pr = r >> 1;
    return pr * 128u + (((((r & 1u) << 6) | kc16) ^ ((pr & 7u) << 4)));
}

// ---------------- PTX helpers (sm_80+ only) ----------------
__device__ __forceinline__ void cp16(uint32_t dst, const void* src) {
    asm volatile("cp.async.cg.shared.global [%0], [%1], 16;" :: "r"(dst), "l"(src));
}
__device__ __forceinline__ void cp_commit() {
    asm volatile("cp.async.commit_group;" ::: "memory");
}
__device__ __forceinline__ void cp_wait2() {
    asm volatile("cp.async.wait_group 2;" ::: "memory");
}
__device__ __forceinline__ void ldsm4(uint32_t& r0, uint32_t& r1, uint32_t& r2, uint32_t& r3,
                                      uint32_t addr) {
    asm volatile("ldmatrix.sync.aligned.m8n8.x4.shared.b16 {%0,%1,%2,%3}, [%4];"
                 : "=r"(r0), "=r"(r1), "=r"(r2), "=r"(r3) : "r"(addr));
}
__device__ __forceinline__ void mma_s8(int* c, const uint32_t* a, const uint32_t* b) {
    asm volatile(
        "mma.sync.aligned.m16n8k32.row.col.s32.s8.s8.s32 "
        "{%0,%1,%2,%3}, {%4,%5,%6,%7}, {%8,%9}, {%0,%1,%2,%3};"
        : "+r"(c[0]), "+r"(c[1]), "+r"(c[2]), "+r"(c[3])
        : "r"(a[0]), "r"(a[1]), "r"(a[2]), "r"(a[3]), "r"(b[0]), "r"(b[1]));
}

__device__ __forceinline__ int q8(float v, float inv, float zp) {
    // match reference: round(x * (1/s) + zp), half-even, then clamp
    float t = __fadd_rn(__fmul_rn(v, inv), zp);
    return (int)fminf(fmaxf(rintf(t), -128.0f), 127.0f);
}
__device__ __forceinline__ uint32_t pack4(int a, int b, int c, int d) {
    return (uint32_t)(a & 255) | ((uint32_t)(b & 255) << 8) |
           ((uint32_t)(c & 255) << 16) | ((uint32_t)(d & 255) << 24);
}

// Decode physical 16B chunk index -> (m, k0) source coordinates (swizzle inverse)
__device__ __forceinline__ void chunk_to_mk(unsigned g, unsigned& m, unsigned& k0) {
    unsigned tile = g >> 9;
    unsigned wo   = (g & 511u) << 4;
    unsigned pr   = wo >> 7;
    unsigned q16  = wo & 127u;
    unsigned lc   = q16 ^ ((pr & 7u) << 4);
    unsigned r    = (pr << 1) | (lc >> 6);
    unsigned kc   = lc & 48u;
    unsigned mt   = tile >> 4, kt = tile & 15u;
    m  = mt * 128u + r;
    k0 = kt * 64u + kc;
}

// ---------------- kernel 1: fused weight prep (first) + quant (coalesced, MLP-8) ----------------
// Blocks [0, 256): weight prep, 4 output channels per block -> finishes early,
//   overlapping its DRAM traffic with the quant ramp instead of forming a tail.
// Blocks [256, 2304): quantize x. Thread owns TWO adjacent physical 16B chunks
//   of g_xq; all 8 source float4 loads are issued before any compute (MLP=8).
__global__ __launch_bounds__(256) void prep_kernel(
    const float* __restrict__ x,
    const float* __restrict__ act_scale,
    const float* __restrict__ act_zp,
    const int*   __restrict__ w,
    const float* __restrict__ wscale,
    const float* __restrict__ bias)
{
    const int tid = threadIdx.x;
    if (blockIdx.x >= WPREP_BLOCKS) {
        // ---------- quant path ----------
        const float inv = 1.0f / act_scale[0];
        const float zp  = act_zp[0];
        unsigned g0 = ((blockIdx.x - WPREP_BLOCKS) * 256u + tid) * 2u;  // first of 2 chunks

        unsigned m0, k00, m1, k01;
        chunk_to_mk(g0,      m0, k00);
        chunk_to_mk(g0 + 1u, m1, k01);

        const float4* s0 = reinterpret_cast<const float4*>(x + (size_t)m0 * KTOT + k00);
        const float4* s1 = reinterpret_cast<const float4*>(x + (size_t)m1 * KTOT + k01);

        // issue all 8 loads before any dependent compute
        float4 v[8];
#pragma unroll
        for (int j = 0; j < 4; j++) v[j] = s0[j];
#pragma unroll
        for (int j = 0; j < 4; j++) v[4 + j] = s1[j];

        uint32_t pk[8];
#pragma unroll
        for (int j = 0; j < 8; j++)
            pk[j] = pack4(q8(v[j].x, inv, zp), q8(v[j].y, inv, zp),
                          q8(v[j].z, inv, zp), q8(v[j].w, inv, zp));

        *reinterpret_cast<uint4*>(g_xq + (size_t)g0 * 16u)        = *reinterpret_cast<uint4*>(&pk[0]);
        *reinterpret_cast<uint4*>(g_xq + (size_t)(g0 + 1u) * 16u) = *reinterpret_cast<uint4*>(&pk[4]);
    } else {
        // ---------- weight prep path ----------
        __shared__ int red[4][2];
        const int bid2 = blockIdx.x;                      // 0..255
        const int s = tid >> 6, t = tid & 63;             // channel slot, lane-in-channel
        const int o = bid2 * 4 + s;

        const int4* wr = reinterpret_cast<const int4*>(w + (size_t)o * KTOT + t * 16);
        int4 p0 = wr[0], p1 = wr[1], p2 = wr[2], p3 = wr[3];

        int sum = p0.x + p0.y + p0.z + p0.w + p1.x + p1.y + p1.z + p1.w
                + p2.x + p2.y + p2.z + p2.w + p3.x + p3.y + p3.z + p3.w;

        uint32_t pk[4];
        pk[0] = pack4(p0.x, p0.y, p0.z, p0.w);
        pk[1] = pack4(p1.x, p1.y, p1.z, p1.w);
        pk[2] = pack4(p2.x, p2.y, p2.z, p2.w);
        pk[3] = pack4(p3.x, p3.y, p3.z, p3.w);

        unsigned k0 = (unsigned)t << 4;
        unsigned ntile = (unsigned)o >> 7, nr = (unsigned)o & 127u;
        unsigned kt = k0 >> 6, kc = k0 & 63u;
        unsigned off = (ntile * 16u + kt) * TILE_BYTES + tile_off(nr, kc);
        *reinterpret_cast<uint4*>(g_wb + off) = *reinterpret_cast<uint4*>(pk);

#pragma unroll
        for (int d = 16; d > 0; d >>= 1) sum += __shfl_down_sync(0xffffffffu, sum, d);
        if ((t & 31) == 0) red[s][t >> 5] = sum;
        __syncthreads();
        if (t == 0) {
            int tot = red[s][0] + red[s][1];
            float alpha = wscale[o] * act_scale[0];
            g_alpha[o] = alpha;
            g_beta[o]  = bias[o] - act_zp[0] * (float)tot * alpha;
        }
    }
}

// ---------------- kernel 2: int8 mma.sync GEMM (R12 proven, at path ceiling) ----------------
// 1024 CTAs (128 mt x 8 nt), 256 threads = 8 warps in 2(m) x 4(n), warp tile 64x32.
// 2 CTAs/SM -> 4 warps per SMSP.
__global__ __launch_bounds__(256, 2) void gemm_kernel(float* __restrict__ out)
{
    extern __shared__ __align__(128) unsigned char smem[];
    const uint32_t Sa = (uint32_t)__cvta_generic_to_shared(smem);
    const uint32_t Sb = Sa + STAGES * TILE_BYTES;

    const int tid = threadIdx.x, wid = tid >> 5, lid = tid & 31;
    const int wm = wid & 1, wn = wid >> 1;       // 2(m) x 4(n)
    const unsigned mt = blockIdx.x >> 3, nt = blockIdx.x & 7u;

    const unsigned char* ag = g_xq + (size_t)mt * KT * TILE_BYTES;
    const unsigned char* bg = g_wb + (size_t)nt * KT * TILE_BYTES;

    uint32_t aoff[4][2], boff[2][2];
    {
        const uint32_t amr = (uint32_t)(wm * 64 + (lid & 15));
        const uint32_t akc = (uint32_t)((lid >> 4) * 16);
#pragma unroll
        for (int f = 0; f < 4; f++)
#pragma unroll
            for (int ks = 0; ks < 2; ks++)
                aoff[f][ks] = tile_off(amr + f * 16u, (uint32_t)(ks * 32) + akc);

        const uint32_t bnr = (uint32_t)(wn * 32 + (lid & 7) + ((lid >> 4) << 3));
        const uint32_t bkc = (uint32_t)(((lid >> 3) & 1) * 16);
#pragma unroll
        for (int gg = 0; gg < 2; gg++)
#pragma unroll
            for (int ks = 0; ks < 2; ks++)
                boff[gg][ks] = tile_off(bnr + gg * 16u, (uint32_t)(ks * 32) + bkc);
    }

    int acc[4][4][4] = {};

#define ISSUE_COPY(st_, kt_)                                                      \
    do {                                                                          \
        uint32_t da = Sa + (uint32_t)(st_) * TILE_BYTES;                          \
        uint32_t db = Sb + (uint32_t)(st_) * TILE_BYTES;                          \
        const unsigned char* sa = ag + (size_t)(kt_) * TILE_BYTES;                \
        const unsigned char* sbp = bg + (size_t)(kt_) * TILE_BYTES;               \
        cp16(da + tid * 16,           sa + tid * 16);                             \
        cp16(da + (tid + 256) * 16,   sa + (tid + 256) * 16);                     \
        cp16(db + tid * 16,           sbp + tid * 16);                            \
        cp16(db + (tid + 256) * 16,   sbp + (tid + 256) * 16);                    \
    } while (0)

#pragma unroll
    for (int p = 0; p < STAGES - 1; p++) { ISSUE_COPY(p, p); cp_commit(); }

    for (int kt = 0; kt < KT; kt++) {
        cp_wait2();
        __syncthreads();
        const int nk = kt + STAGES - 1;
        if (nk < KT) ISSUE_COPY(nk & (STAGES - 1), nk);
        cp_commit();

        const uint32_t ba = Sa + (uint32_t)(kt & (STAGES - 1)) * TILE_BYTES;
        const uint32_t bb = Sb + (uint32_t)(kt & (STAGES - 1)) * TILE_BYTES;

#pragma unroll
        for (int ks = 0; ks < 2; ks++) {
            uint32_t a[4][4], b[4][2];
#pragma unroll
            for (int f = 0; f < 4; f++)
                ldsm4(a[f][0], a[f][1], a[f][2], a[f][3], ba + aoff[f][ks]);
#pragma unroll
            for (int gg = 0; gg < 2; gg++)
                ldsm4(b[2 * gg][0], b[2 * gg][1], b[2 * gg + 1][0], b[2 * gg + 1][1],
                      bb + boff[gg][ks]);
#pragma unroll
            for (int f = 0; f < 4; f++)
#pragma unroll
                for (int g = 0; g < 4; g++)
                    mma_s8(acc[f][g], a[f], b[g]);
        }
    }

    // -------- epilogue: s32 -> float, *alpha + beta, float2 stores --------
    const int row = lid >> 2, colp = (lid & 3) << 1;
    const int ncol0 = (int)(nt * 128) + wn * 32 + colp;

    float2 al[4], be[4];
#pragma unroll
    for (int g = 0; g < 4; g++) {
        al[g] = *reinterpret_cast<const float2*>(&g_alpha[ncol0 + g * 8]);
        be[g] = *reinterpret_cast<const float2*>(&g_beta[ncol0 + g * 8]);
    }

#pragma unroll
    for (int f = 0; f < 4; f++) {
        const size_t m0 = (size_t)(mt * 128 + wm * 64 + f * 16 + row);
        float* o0 = out + m0 * NTOT + ncol0;
        float* o1 = o0 + 8 * NTOT;
#pragma unroll
        for (int g = 0; g < 4; g++) {
            float2 v0, v1;
            v0.x = (float)acc[f][g][0] * al[g].x + be[g].x;
            v0.y = (float)acc[f][g][1] * al[g].y + be[g].y;
            v1.x = (float)acc[f][g][2] * al[g].x + be[g].x;
            v1.y = (float)acc[f][g][3] * al[g].y + be[g].y;
            *reinterpret_cast<float2*>(o0 + g * 8) = v0;
            *reinterpret_cast<float2*>(o1 + g * 8) = v1;
        }
    }
#undef ISSUE_COPY
}

// ---------------- launch ----------------
extern "C" void kernel_launch(void* const* d_in, const int* in_sizes, int n_in,
                              void* d_out, int out_size)
{
    const float* x      = (const float*)d_in[0];
    const int*   w      = (const int*)d_in[1];
    const float* wscale = (const float*)d_in[2];
    const float* ascale = (const float*)d_in[3];
    const float* azp    = (const float*)d_in[4];
    const float* bias   = (const float*)d_in[5];
    float* out = (float*)d_out;

    const int smem_bytes = 2 * STAGES * TILE_BYTES;   // 64 KB
    cudaFuncSetAttribute(gemm_kernel, cudaFuncAttributeMaxDynamicSharedMemorySize, smem_bytes);

    prep_kernel<<<WPREP_BLOCKS + QUANT_BLOCKS, 256>>>(x, ascale, azp, w, wscale, bias);
    gemm_kernel<<<MT * NT, 256, smem_bytes>>>(out);
}

// round 14
// speedup vs baseline: 1.0883x; 1.0883x over previous
#include <cuda_runtime.h>
#include <cstdint>

// ---------------- problem constants ----------------
#define MTOT 16384
#define KTOT 1024
#define NTOT 1024

#define BM 128
#define BN 128
#define KT 16             /* 64-byte k-tiles */
#define MT (MTOT / BM)    /* 128 m-tiles  */
#define NT (NTOT / BN)    /* 8 n-tiles    */

#define STAGES 4
#define TILE_BYTES (128 * 64)   /* 8192 */

#define QUANT_BLOCKS 4096       /* 1 physical 16B chunk per thread (proven roofline config) */
#define WPREP_BLOCKS 256        /* 4 output channels per 256-thread block */

// ---------------- scratch (device globals; no allocation allowed) ----------------
__device__ __align__(16) unsigned char g_xq[(size_t)MTOT * KTOT];  // 16 MB int8, tiled+swizzled
__device__ __align__(16) unsigned char g_wb[(size_t)NTOT * KTOT];  // 1 MB int8, tiled+swizzled
__device__ float g_alpha[NTOT];
__device__ float g_beta[NTOT];

// Tile layout: [128 rows r][64 k-bytes] packed as 64 physical rows of 128B:
//   off(r, kc16) = (r>>1)*128 + ( (((r&1)<<6) | kc16) ^ (((r>>1)&7)<<4) )
__device__ __forceinline__ uint32_t tile_off(uint32_t r, uint32_t kc16) {
    uint32_t pr = r >> 1;
    return pr * 128u + (((((r & 1u) << 6) | kc16) ^ ((pr & 7u) << 4)));
}

// ---------------- PTX helpers (sm_80/sm_90 only; no 'a'-gated instructions) ----------------
__device__ __forceinline__ void cp16(uint32_t dst, const void* src) {
    asm volatile("cp.async.cg.shared.global [%0], [%1], 16;" :: "r"(dst), "l"(src));
}
__device__ __forceinline__ void cp_commit() {
    asm volatile("cp.async.commit_group;" ::: "memory");
}
__device__ __forceinline__ void cp_wait2() {
    asm volatile("cp.async.wait_group 2;" ::: "memory");
}
__device__ __forceinline__ void ldsm4(uint32_t& r0, uint32_t& r1, uint32_t& r2, uint32_t& r3,
                                      uint32_t addr) {
    asm volatile("ldmatrix.sync.aligned.m8n8.x4.shared.b16 {%0,%1,%2,%3}, [%4];"
                 : "=r"(r0), "=r"(r1), "=r"(r2), "=r"(r3) : "r"(addr));
}
__device__ __forceinline__ void mma_s8(int* c, const uint32_t* a, const uint32_t* b) {
    asm volatile(
        "mma.sync.aligned.m16n8k32.row.col.s32.s8.s8.s32 "
        "{%0,%1,%2,%3}, {%4,%5,%6,%7}, {%8,%9}, {%0,%1,%2,%3};"
        : "+r"(c[0]), "+r"(c[1]), "+r"(c[2]), "+r"(c[3])
        : "r"(a[0]), "r"(a[1]), "r"(a[2]), "r"(a[3]), "r"(b[0]), "r"(b[1]));
}
// PDL (sm_90+): primary releases dependents early; dependent waits before touching
// primary's output. Serial-equivalent correctness.
__device__ __forceinline__ void pdl_launch_dependents() {
    asm volatile("griddepcontrol.launch_dependents;" ::: "memory");
}
__device__ __forceinline__ void pdl_wait() {
    asm volatile("griddepcontrol.wait;" ::: "memory");
}

__device__ __forceinline__ int q8(float v, float inv, float zp) {
    // match reference: round(x * (1/s) + zp), half-even, then clamp
    float t = __fadd_rn(__fmul_rn(v, inv), zp);
    return (int)fminf(fmaxf(rintf(t), -128.0f), 127.0f);
}
__device__ __forceinline__ uint32_t pack4(int a, int b, int c, int d) {
    return (uint32_t)(a & 255) | ((uint32_t)(b & 255) << 8) |
           ((uint32_t)(c & 255) << 16) | ((uint32_t)(d & 255) << 24);
}

// ---------------- kernel 1: fused quant (coalesced writes) + weight prep (R12 proven) ----------------
__global__ __launch_bounds__(256) void prep_kernel(
    const float* __restrict__ x,
    const float* __restrict__ act_scale,
    const float* __restrict__ act_zp,
    const int*   __restrict__ w,
    const float* __restrict__ wscale,
    const float* __restrict__ bias)
{
    const int tid = threadIdx.x;
    pdl_launch_dependents();   // release the GEMM grid immediately; it self-syncs before reads
    if (blockIdx.x < QUANT_BLOCKS) {
        const float inv = 1.0f / act_scale[0];
        const float zp  = act_zp[0];
        unsigned g = blockIdx.x * 256u + tid;       // physical 16B chunk index
        unsigned tile = g >> 9;
        unsigned wo   = (g & 511u) << 4;
        unsigned pr   = wo >> 7;
        unsigned q16  = wo & 127u;
        unsigned lc   = q16 ^ ((pr & 7u) << 4);
        unsigned r    = (pr << 1) | (lc >> 6);
        unsigned kc   = lc & 48u;
        unsigned mt   = tile >> 4, kt = tile & 15u;
        unsigned m    = mt * 128u + r;
        unsigned k0   = kt * 64u + kc;

        const float4* src = reinterpret_cast<const float4*>(x + (size_t)m * KTOT + k0);
        uint32_t pk[4];
#pragma unroll
        for (int j = 0; j < 4; j++) {
            float4 v = src[j];
            pk[j] = pack4(q8(v.x, inv, zp), q8(v.y, inv, zp), q8(v.z, inv, zp), q8(v.w, inv, zp));
        }
        *reinterpret_cast<uint4*>(g_xq + (size_t)g * 16u) = *reinterpret_cast<uint4*>(pk);
    } else {
        __shared__ int red[4][2];
        const int bid2 = blockIdx.x - QUANT_BLOCKS;
        const int s = tid >> 6, t = tid & 63;
        const int o = bid2 * 4 + s;

        const int4* wr = reinterpret_cast<const int4*>(w + (size_t)o * KTOT + t * 16);
        int4 p0 = wr[0], p1 = wr[1], p2 = wr[2], p3 = wr[3];

        int sum = p0.x + p0.y + p0.z + p0.w + p1.x + p1.y + p1.z + p1.w
                + p2.x + p2.y + p2.z + p2.w + p3.x + p3.y + p3.z + p3.w;

        uint32_t pk[4];
        pk[0] = pack4(p0.x, p0.y, p0.z, p0.w);
        pk[1] = pack4(p1.x, p1.y, p1.z, p1.w);
        pk[2] = pack4(p2.x, p2.y, p2.z, p2.w);
        pk[3] = pack4(p3.x, p3.y, p3.z, p3.w);

        unsigned k0 = (unsigned)t << 4;
        unsigned ntile = (unsigned)o >> 7, nr = (unsigned)o & 127u;
        unsigned kt = k0 >> 6, kc = k0 & 63u;
        unsigned off = (ntile * 16u + kt) * TILE_BYTES + tile_off(nr, kc);
        *reinterpret_cast<uint4*>(g_wb + off) = *reinterpret_cast<uint4*>(pk);

#pragma unroll
        for (int d = 16; d > 0; d >>= 1) sum += __shfl_down_sync(0xffffffffu, sum, d);
        if ((t & 31) == 0) red[s][t >> 5] = sum;
        __syncthreads();
        if (t == 0) {
            int tot = red[s][0] + red[s][1];
            float alpha = wscale[o] * act_scale[0];
            g_alpha[o] = alpha;
            g_beta[o]  = bias[o] - act_zp[0] * (float)tot * alpha;
        }
    }
}

// ---------------- kernel 2: int8 mma.sync GEMM (R12 proven core + PDL prologue overlap) ----------------
// 1024 CTAs (128 mt x 8 nt), 256 threads = 8 warps in 2(m) x 4(n), warp tile 64x32.
// 2 CTAs/SM -> 4 warps per SMSP. Launched with PDL: setup overlaps prep's tail;
// griddepcontrol.wait fences before the first global read of prep's outputs.
__global__ __launch_bounds__(256, 2) void gemm_kernel(float* __restrict__ out)
{
    extern __shared__ __align__(128) unsigned char smem[];
    const uint32_t Sa = (uint32_t)__cvta_generic_to_shared(smem);
    const uint32_t Sb = Sa + STAGES * TILE_BYTES;

    const int tid = threadIdx.x, wid = tid >> 5, lid = tid & 31;
    const int wm = wid & 1, wn = wid >> 1;       // 2(m) x 4(n)
    const unsigned mt = blockIdx.x >> 3, nt = blockIdx.x & 7u;

    const unsigned char* ag = g_xq + (size_t)mt * KT * TILE_BYTES;
    const unsigned char* bg = g_wb + (size_t)nt * KT * TILE_BYTES;

    uint32_t aoff[4][2], boff[2][2];
    {
        const uint32_t amr = (uint32_t)(wm * 64 + (lid & 15));
        const uint32_t akc = (uint32_t)((lid >> 4) * 16);
#pragma unroll
        for (int f = 0; f < 4; f++)
#pragma unroll
            for (int ks = 0; ks < 2; ks++)
                aoff[f][ks] = tile_off(amr + f * 16u, (uint32_t)(ks * 32) + akc);

        const uint32_t bnr = (uint32_t)(wn * 32 + (lid & 7) + ((lid >> 4) << 3));
        const uint32_t bkc = (uint32_t)(((lid >> 3) & 1) * 16);
#pragma unroll
        for (int gg = 0; gg < 2; gg++)
#pragma unroll
            for (int ks = 0; ks < 2; ks++)
                boff[gg][ks] = tile_off(bnr + gg * 16u, (uint32_t)(ks * 32) + bkc);
    }

    int acc[4][4][4] = {};

#define ISSUE_COPY(st_, kt_)                                                      \
    do {                                                                          \
        uint32_t da = Sa + (uint32_t)(st_) * TILE_BYTES;                          \
        uint32_t db = Sb + (uint32_t)(st_) * TILE_BYTES;                          \
        const unsigned char* sa = ag + (size_t)(kt_) * TILE_BYTES;                \
        const unsigned char* sbp = bg + (size_t)(kt_) * TILE_BYTES;               \
        cp16(da + tid * 16,           sa + tid * 16);                             \
        cp16(da + (tid + 256) * 16,   sa + (tid + 256) * 16);                     \
        cp16(db + tid * 16,           sbp + tid * 16);                            \
        cp16(db + (tid + 256) * 16,   sbp + (tid + 256) * 16);                    \
    } while (0)

    // all setup done; now fence against prep before touching its outputs
    pdl_wait();

#pragma unroll
    for (int p = 0; p < STAGES - 1; p++) { ISSUE_COPY(p, p); cp_commit(); }

    for (int kt = 0; kt < KT; kt++) {
        cp_wait2();
        __syncthreads();
        const int nk = kt + STAGES - 1;
        if (nk < KT) ISSUE_COPY(nk & (STAGES - 1), nk);
        cp_commit();

        const uint32_t ba = Sa + (uint32_t)(kt & (STAGES - 1)) * TILE_BYTES;
        const uint32_t bb = Sb + (uint32_t)(kt & (STAGES - 1)) * TILE_BYTES;

#pragma unroll
        for (int ks = 0; ks < 2; ks++) {
            uint32_t a[4][4], b[4][2];
#pragma unroll
            for (int f = 0; f < 4; f++)
                ldsm4(a[f][0], a[f][1], a[f][2], a[f][3], ba + aoff[f][ks]);
#pragma unroll
            for (int gg = 0; gg < 2; gg++)
                ldsm4(b[2 * gg][0], b[2 * gg][1], b[2 * gg + 1][0], b[2 * gg + 1][1],
                      bb + boff[gg][ks]);
#pragma unroll
            for (int f = 0; f < 4; f++)
#pragma unroll
                for (int g = 0; g < 4; g++)
                    mma_s8(acc[f][g], a[f], b[g]);
        }
    }

    // -------- epilogue: s32 -> float, *alpha + beta, float2 stores --------
    const int row = lid >> 2, colp = (lid & 3) << 1;
    const int ncol0 = (int)(nt * 128) + wn * 32 + colp;

    float2 al[4], be[4];
#pragma unroll
    for (int g = 0; g < 4; g++) {
        al[g] = *reinterpret_cast<const float2*>(&g_alpha[ncol0 + g * 8]);
        be[g] = *reinterpret_cast<const float2*>(&g_beta[ncol0 + g * 8]);
    }

#pragma unroll
    for (int f = 0; f < 4; f++) {
        const size_t m0 = (size_t)(mt * 128 + wm * 64 + f * 16 + row);
        float* o0 = out + m0 * NTOT + ncol0;
        float* o1 = o0 + 8 * NTOT;
#pragma unroll
        for (int g = 0; g < 4; g++) {
            float2 v0, v1;
            v0.x = (float)acc[f][g][0] * al[g].x + be[g].x;
            v0.y = (float)acc[f][g][1] * al[g].y + be[g].y;
            v1.x = (float)acc[f][g][2] * al[g].x + be[g].x;
            v1.y = (float)acc[f][g][3] * al[g].y + be[g].y;
            *reinterpret_cast<float2*>(o0 + g * 8) = v0;
            *reinterpret_cast<float2*>(o1 + g * 8) = v1;
        }
    }
#undef ISSUE_COPY
}

// ---------------- launch ----------------
extern "C" void kernel_launch(void* const* d_in, const int* in_sizes, int n_in,
                              void* d_out, int out_size)
{
    const float* x      = (const float*)d_in[0];
    const int*   w      = (const int*)d_in[1];
    const float* wscale = (const float*)d_in[2];
    const float* ascale = (const float*)d_in[3];
    const float* azp    = (const float*)d_in[4];
    const float* bias   = (const float*)d_in[5];
    float* out = (float*)d_out;

    const int smem_bytes = 2 * STAGES * TILE_BYTES;   // 64 KB
    cudaFuncSetAttribute(gemm_kernel, cudaFuncAttributeMaxDynamicSharedMemorySize, smem_bytes);

    prep_kernel<<<QUANT_BLOCKS + WPREP_BLOCKS, 256>>>(x, ascale, azp, w, wscale, bias);

    // GEMM with programmatic dependent launch: overlaps its launch/prologue with
    // prep's tail; griddepcontrol.wait in-kernel enforces serial-equivalent ordering.
    cudaLaunchConfig_t cfg = {};
    cfg.gridDim = dim3(MT * NT, 1, 1);
    cfg.blockDim = dim3(256, 1, 1);
    cfg.dynamicSmemBytes = (size_t)smem_bytes;
    cfg.stream = 0;
    cudaLaunchAttribute attrs[1];
    attrs[0].id = cudaLaunchAttributeProgrammaticStreamSerialization;
    attrs[0].val.programmaticStreamSerializationAllowed = 1;
    cfg.attrs = attrs;
    cfg.numAttrs = 1;
    cudaLaunchKernelEx(&cfg, gemm_kernel, out);
}